// round 16
// baseline (speedup 1.0000x reference)
#include <cuda_runtime.h>
#include <cuda_fp16.h>
#include <math.h>
#include <stdint.h>

#define CC      384
#define SIDE    56
#define HWD     3136
#define TOKENS  100352
#define NHEADS  12
#define NWIN    2048
#define HIDDEN  1536
#define QKVN    1152
#define LN_EPS  1e-5f
#define ATT_SCALE 0.17677669529663687f

// ---------------- scratch ----------------
__device__ uint32_t g_xn_f [(size_t)TOKENS * CC / 2];
__device__ uint32_t g_att_f[(size_t)TOKENS * CC / 2];
__device__ uint32_t g_s2_f [(size_t)TOKENS * CC / 2];
__device__ uint32_t g_hid_f[(size_t)TOKENS * HIDDEN / 2];
__device__ uint32_t g_qkv_w[(size_t)TOKENS * QKVN / 2];   // fp16 row-major
__device__ uint32_t g_seq1h[(size_t)TOKENS * CC / 2];     // fp16 row-major
__device__ uint32_t g_wq[(size_t)QKVN * CC / 2];
__device__ uint32_t g_wp[(size_t)CC * CC / 2];
__device__ uint32_t g_w1[(size_t)HIDDEN * CC / 2];
__device__ uint32_t g_w2[(size_t)CC * HIDDEN / 2];
__device__ float    g_biasx[NHEADS * 49 * 52];            // expanded rel-pos bias

// A-fragment word address
__device__ __forceinline__ size_t afrag_word(int m, int k, int K) {
    int R = m >> 7, q = (m & 127) >> 4, hm = (m >> 3) & 1, g = m & 7;
    int ko = k >> 4, chi = (k >> 3) & 1, c = (k & 7) >> 1;
    return (((size_t)R * (K / 16) + ko) * 8 + q) * 128 + g * 16 + c * 4 + chi * 2 + hm;
}
// B-fragment word address
__device__ __forceinline__ size_t bfrag_word(int n, int k, int K) {
    int RN = n >> 7, nq = (n & 127) >> 3, g = n & 7;
    int ko = k >> 4, chi = (k >> 3) & 1, c = (k & 7) >> 1;
    return (((size_t)RN * (K / 16) + ko) * 16 + nq) * 64 + g * 8 + c * 2 + chi;
}

__device__ __forceinline__ uint32_t pack_h2(float a, float b) {
    __half2 h = __floats2half2_rn(a, b);
    return *reinterpret_cast<uint32_t*>(&h);
}
__device__ __forceinline__ float2 unpack_h2(uint32_t w) {
    __half2 h = *reinterpret_cast<__half2*>(&w);
    return __half22float2(h);
}

__device__ __forceinline__ void mma_f16(float* d, const uint32_t* a, const uint32_t* b) {
    asm volatile(
        "mma.sync.aligned.m16n8k16.row.col.f32.f16.f16.f32 "
        "{%0,%1,%2,%3},{%4,%5,%6,%7},{%8,%9},{%0,%1,%2,%3};"
        : "+f"(d[0]), "+f"(d[1]), "+f"(d[2]), "+f"(d[3])
        : "r"(a[0]), "r"(a[1]), "r"(a[2]), "r"(a[3]), "r"(b[0]), "r"(b[1]));
}

#define CPA16(sa, gp)  asm volatile("cp.async.cg.shared.global [%0], [%1], 16;" :: "r"(sa), "l"(gp))
#define CPA_COMMIT()   asm volatile("cp.async.commit_group;")
#define CPA_WAIT(n)    asm volatile("cp.async.wait_group %0;" :: "n"(n))

// ---------------- weight pack + bias expand ----------------
__device__ __forceinline__ void pack_one(const float* W, uint32_t* dst, int N, int K, int idx) {
    if (idx >= N * (K / 2)) return;
    int n = idx / (K / 2);
    int k = (idx - n * (K / 2)) * 2;
    dst[bfrag_word(n, k, K)] = pack_h2(W[(size_t)n * K + k], W[(size_t)n * K + k + 1]);
}
__global__ void pack_a_kernel(const float* __restrict__ Wq, uint32_t* dq,
                              const float* __restrict__ Wp, uint32_t* dp,
                              const float* __restrict__ bias_table) {
    int bid = blockIdx.x;
    if (bid < 864) { pack_one(Wq, dq, QKVN, CC, bid * 256 + threadIdx.x); return; }
    if (bid < 1152) { pack_one(Wp, dp, CC, CC, (bid - 864) * 256 + threadIdx.x); return; }
    int t = (bid - 1152) * 256 + threadIdx.x;
    if (t >= NHEADS * 49 * 52) return;
    int h = t / 2548;
    int rem = t - h * 2548;
    int n = rem / 52, m = rem - n * 52;
    if (m < 49) {
        int in = n / 7, jn = n - in * 7;
        int im = m / 7, jm = m - im * 7;
        g_biasx[t] = bias_table[((in - im + 6) * 13 + (jn - jm + 6)) * NHEADS + h];
    }
}
__global__ void pack_b_kernel(const float* __restrict__ W1, uint32_t* d1,
                              const float* __restrict__ W2, uint32_t* d2) {
    int bid = blockIdx.x;
    if (bid < 1152) pack_one(W1, d1, HIDDEN, CC, bid * 256 + threadIdx.x);
    else            pack_one(W2, d2, CC, HIDDEN, (bid - 1152) * 256 + threadIdx.x);
}

// ---------------- LayerNorm -> g_xn_f (A-fragment fp16) --------------------
__global__ __launch_bounds__(256) void ln_xn_kernel(
    const float* __restrict__ x,
    const float* __restrict__ lng,
    const float* __restrict__ lnb)
{
    extern __shared__ float S[];               // [384][33]
    __shared__ float red[2][8][32];
    __shared__ float s_mu[32], s_rs[32];
    int blk = blockIdx.x;
    int b   = blk / 98;
    int t0  = (blk % 98) * 32;
    int tid = threadIdx.x;

    const float* xb = x + (size_t)b * CC * HWD + t0;
    #pragma unroll 4
    for (int it = 0; it < 48; it++) {
        int idx = it * 256 + tid;
        int c = idx >> 5, t = idx & 31;
        S[c * 33 + t] = xb[(size_t)c * HWD + t];
    }
    __syncthreads();

    int t = tid & 31, p = tid >> 5;
    float s = 0.f, ss = 0.f;
    #pragma unroll 8
    for (int j = 0; j < 48; j++) {
        float v = S[(p + 8 * j) * 33 + t];
        s += v; ss += v * v;
    }
    red[0][p][t] = s; red[1][p][t] = ss;
    __syncthreads();
    if (p == 0) {
        float Sm = 0.f, SS = 0.f;
        #pragma unroll
        for (int q = 0; q < 8; q++) { Sm += red[0][q][t]; SS += red[1][q][t]; }
        float mu = Sm * (1.0f / CC);
        float var = SS * (1.0f / CC) - mu * mu;
        s_mu[t] = mu;
        s_rs[t] = rsqrtf(var + LN_EPS);
    }
    __syncthreads();

    int m_base = b * HWD + t0;
    int R = m_base >> 7, q0 = (m_base & 127) >> 4;
    int inner = tid & 127;
    int g = inner >> 4, c = (inner >> 2) & 3, chi = (inner >> 1) & 1, hm = inner & 1;
    #pragma unroll 4
    for (int j = 0; j < 24; j++) {
        int combo = j * 2 + (tid >> 7);
        int ko = combo >> 1, qi = combo & 1;
        int tl = qi * 16 + hm * 8 + g;
        int k  = ko * 16 + chi * 8 + c * 2;
        float mu = s_mu[tl], rs = s_rs[tl];
        float v0 = (S[k * 33 + tl]       - mu) * rs * __ldg(&lng[k])     + __ldg(&lnb[k]);
        float v1 = (S[(k + 1) * 33 + tl] - mu) * rs * __ldg(&lng[k + 1]) + __ldg(&lnb[k + 1]);
        g_xn_f[(((size_t)R * 24 + ko) * 8 + (q0 + qi)) * 128 + inner] = pack_h2(v0, v1);
    }
}

// ---------------- fp16 tensor-core GEMM (128 thr, 2x2 warps of 64x64) ------
template<int MODE>
__global__ __launch_bounds__(128, 2) void hgemm(
    const float* __restrict__ x,
    const uint32_t* __restrict__ Bw,
    const float* __restrict__ bias,
    float* __restrict__ out)
{
    constexpr int K    = (MODE == 3) ? HIDDEN : CC;
    constexpr int KD16 = K / 16;
    constexpr int KT   = K / 64;
    const int m0  = blockIdx.y * 128;
    const int n0  = blockIdx.x * 128;
    const int tid = threadIdx.x;
    const int lane = tid & 31, warp = tid >> 5;
    const int wr = warp >> 1, wc = warp & 1;   // 2x2 warps; warp tile 64x64
    const int g  = lane >> 2, c = lane & 3;

    extern __shared__ uint32_t smu[];
    const uint32_t smem_base = (uint32_t)__cvta_generic_to_shared(smu);
    float* smf = (float*)smu;

    const uint32_t* Asrc = (MODE == 0) ? g_xn_f : (MODE == 1) ? g_att_f
                         : (MODE == 2) ? g_s2_f : g_hid_f;
    const size_t Abase = (size_t)(m0 >> 7) * KD16 * 1024;
    const size_t Bbase = (size_t)(n0 >> 7) * KD16 * 1024;

    float acc[4][8][4];
    #pragma unroll
    for (int i = 0; i < 4; i++)
        #pragma unroll
        for (int j = 0; j < 8; j++)
            #pragma unroll
            for (int e = 0; e < 4; e++) acc[i][j][e] = 0.f;

    auto load_tile = [&](int kt) {
        int st = kt % 3;
        const uint32_t* Ag = Asrc + Abase + (size_t)kt * 4096;
        const uint32_t* Bg = Bw   + Bbase + (size_t)kt * 4096;
        uint32_t As = smem_base + st * 32768;
        #pragma unroll
        for (int i = 0; i < 8; i++) {
            CPA16(As + i * 2048 + tid * 16,         Ag + i * 512 + tid * 4);
            CPA16(As + 16384 + i * 2048 + tid * 16, Bg + i * 512 + tid * 4);
        }
        CPA_COMMIT();
    };

    auto ldfrag = [&](const uint32_t* S, int kl, uint4* af, uint2* bf) {
        const uint32_t* A = S + kl * 1024;
        const uint32_t* B = S + 4096 + kl * 1024;
        #pragma unroll
        for (int mi = 0; mi < 4; mi++)
            af[mi] = *(const uint4*)(A + (wr * 4 + mi) * 128 + g * 16 + c * 4);
        #pragma unroll
        for (int ni = 0; ni < 8; ni++)
            bf[ni] = *(const uint2*)(B + (wc * 8 + ni) * 64 + g * 8 + c * 2);
    };

    auto compute = [&](int kt) {
        const uint32_t* S = smu + (kt % 3) * 8192;
        uint4 af[2][4];
        uint2 bf[2][8];
        ldfrag(S, 0, af[0], bf[0]);
        #pragma unroll
        for (int kl = 0; kl < 4; kl++) {
            int cur = kl & 1;
            if (kl < 3) ldfrag(S, kl + 1, af[cur ^ 1], bf[cur ^ 1]);
            #pragma unroll
            for (int mi = 0; mi < 4; mi++)
                #pragma unroll
                for (int ni = 0; ni < 8; ni++)
                    mma_f16(acc[mi][ni], &af[cur][mi].x, &bf[cur][ni].x);
        }
    };

    load_tile(0);
    load_tile(1);
    load_tile(2);
    for (int kt = 0; kt < KT; kt++) {
        CPA_WAIT(2);
        __syncthreads();
        compute(kt);
        __syncthreads();
        if (kt + 3 < KT) load_tile(kt + 3); else CPA_COMMIT();
    }
    CPA_WAIT(0);
    __syncthreads();

    // ---- epilogues ----
    if constexpr (MODE == 0) {
        #pragma unroll
        for (int mi = 0; mi < 4; mi++) {
            #pragma unroll
            for (int ni = 0; ni < 8; ni++) {
                int n = n0 + wc * 64 + ni * 8 + 2 * c;
                float b0 = __ldg(&bias[n]), b1 = __ldg(&bias[n + 1]);
                #pragma unroll
                for (int hm = 0; hm < 2; hm++) {
                    int m = m0 + wr * 64 + mi * 16 + hm * 8 + g;
                    g_qkv_w[(size_t)m * (QKVN / 2) + (n >> 1)] =
                        pack_h2(acc[mi][ni][2 * hm] + b0, acc[mi][ni][2 * hm + 1] + b1);
                }
            }
        }
    } else if constexpr (MODE == 2) {
        #pragma unroll
        for (int mi = 0; mi < 4; mi++) {
            int q = wr * 4 + mi;
            #pragma unroll
            for (int np = 0; np < 4; np++) {
                int koW = (n0 >> 4) + wc * 4 + np;
                size_t base = (((size_t)(m0 >> 7) * (HIDDEN / 16) + koW) * 8 + q) * 128;
                float v[2][4];
                #pragma unroll
                for (int chi = 0; chi < 2; chi++) {
                    int ni = np * 2 + chi;
                    int n = n0 + wc * 64 + ni * 8 + 2 * c;
                    float b0 = __ldg(&bias[n]), b1 = __ldg(&bias[n + 1]);
                    #pragma unroll
                    for (int e = 0; e < 4; e++) {
                        float t = acc[mi][ni][e] + ((e & 1) ? b1 : b0);
                        v[chi][e] = 0.5f * t * (1.0f + erff(t * 0.70710678118654752f));
                    }
                }
                uint4 wrd;
                wrd.x = pack_h2(v[0][0], v[0][1]);
                wrd.y = pack_h2(v[0][2], v[0][3]);
                wrd.z = pack_h2(v[1][0], v[1][1]);
                wrd.w = pack_h2(v[1][2], v[1][3]);
                *(uint4*)(g_hid_f + base + g * 16 + c * 4) = wrd;
            }
        }
    } else if constexpr (MODE == 1) {
        float* Xs = smf;
        {
            int m = m0 + tid;
            int bb = m / HWD, hw = m % HWD;
            const float* xb = x + (size_t)bb * CC * HWD + hw;
            #pragma unroll 8
            for (int j = 0; j < 128; j++)
                Xs[tid * 132 + j] = xb[(size_t)(n0 + j) * HWD];
        }
        __syncthreads();
        #pragma unroll
        for (int mi = 0; mi < 4; mi++) {
            #pragma unroll
            for (int ni = 0; ni < 8; ni++) {
                int n  = n0 + wc * 64 + ni * 8 + 2 * c;
                int cn = wc * 64 + ni * 8 + 2 * c;
                float b0 = __ldg(&bias[n]), b1 = __ldg(&bias[n + 1]);
                #pragma unroll
                for (int hm = 0; hm < 2; hm++) {
                    int r = wr * 64 + mi * 16 + hm * 8 + g;
                    int m = m0 + r;
                    float v0 = acc[mi][ni][2 * hm]     + b0 + Xs[r * 132 + cn];
                    float v1 = acc[mi][ni][2 * hm + 1] + b1 + Xs[r * 132 + cn + 1];
                    g_seq1h[((size_t)m * CC + n) >> 1] = pack_h2(v0, v1);
                }
            }
        }
    } else {  // MODE 3
        float* Cs = smf;
        #pragma unroll
        for (int mi = 0; mi < 4; mi++) {
            #pragma unroll
            for (int ni = 0; ni < 8; ni++) {
                int n  = n0 + wc * 64 + ni * 8 + 2 * c;
                int cn = wc * 64 + ni * 8 + 2 * c;
                float b0 = __ldg(&bias[n]), b1 = __ldg(&bias[n + 1]);
                #pragma unroll
                for (int hm = 0; hm < 2; hm++) {
                    int r = wr * 64 + mi * 16 + hm * 8 + g;
                    int m = m0 + r;
                    float2 s2 = unpack_h2(g_s2_f[afrag_word(m, n, CC)]);
                    Cs[r * 132 + cn]     = acc[mi][ni][2 * hm]     + b0 + s2.x;
                    Cs[r * 132 + cn + 1] = acc[mi][ni][2 * hm + 1] + b1 + s2.y;
                }
            }
        }
        __syncthreads();
        int m = m0 + tid;
        int bb = m / HWD, hw = m % HWD;
        float* ob = out + (size_t)bb * CC * HWD + hw;
        #pragma unroll 8
        for (int j = 0; j < 128; j++)
            ob[(size_t)(n0 + j) * HWD] = Cs[tid * 132 + j];
    }
}

// ---------------- windowed attention (tensor-core mma) ---------------------
__global__ __launch_bounds__(256) void attn_kernel() {
    int wh = blockIdx.x;
    int w  = wh / NHEADS;
    int h  = wh - w * NHEADS;
    int b  = w >> 6;
    int wri = w & 63;
    int nh = wri >> 3, nw = wri & 7;
    int tid = threadIdx.x;
    const int lane = tid & 31, warp = tid >> 5;
    const int g = lane >> 2, c = lane & 3;

    __shared__ uint32_t qs[64 * 20];
    __shared__ uint32_t ks[64 * 20];
    __shared__ uint32_t vt[32 * 36];
    __shared__ uint32_t ps[64 * 36];
    __shared__ float    ss[49 * 52];
    __shared__ int      gtok[49];
    __half* vth = (__half*)vt;

    if (tid < 49) {
        int i = tid / 7, j = tid - i * 7;
        gtok[tid] = b * HWD + (nh * 7 + i) * SIDE + (nw * 7 + j);
    }
    // prefill score buffer with expanded bias (coalesced)
    {
        const float* bx = g_biasx + h * 2548;
        for (int idx = tid; idx < 49 * 52; idx += 256) ss[idx] = bx[idx];
    }
    __syncthreads();

    for (int idx = tid; idx < 49 * 16; idx += 256) {
        int n = idx >> 4, dp = idx & 15;
        size_t base = (size_t)gtok[n] * (QKVN / 2) + h * 16 + dp;
        qs[n * 20 + dp] = g_qkv_w[base];
        ks[n * 20 + dp] = g_qkv_w[base + 192];
        uint32_t vv = g_qkv_w[base + 384];
        __half2 hv = *reinterpret_cast<__half2*>(&vv);
        vth[(2 * dp) * 72 + n]     = __low2half(hv);
        vth[(2 * dp + 1) * 72 + n] = __high2half(hv);
    }
    for (int t = tid; t < 32 * 15; t += 256) {
        int ch = t / 15, tt = 49 + (t - ch * 15);
        vth[ch * 72 + tt] = __float2half(0.f);
    }
    __syncthreads();

    const int mt = warp >> 1;
    const int ntb = (warp & 1) * 4;
    const int r0 = mt * 16 + g, r1 = r0 + 8;
    {
        float sacc[4][4];
        #pragma unroll
        for (int i = 0; i < 4; i++)
            #pragma unroll
            for (int e = 0; e < 4; e++) sacc[i][e] = 0.f;
        #pragma unroll
        for (int ks2 = 0; ks2 < 2; ks2++) {
            uint32_t a[4];
            a[0] = qs[r0 * 20 + ks2 * 8 + c];
            a[1] = qs[r1 * 20 + ks2 * 8 + c];
            a[2] = qs[r0 * 20 + ks2 * 8 + c + 4];
            a[3] = qs[r1 * 20 + ks2 * 8 + c + 4];
            #pragma unroll
            for (int nt = 0; nt < 4; nt++) {
                int nrow = (ntb + nt) * 8 + g;
                uint32_t bb2[2];
                bb2[0] = ks[nrow * 20 + ks2 * 8 + c];
                bb2[1] = ks[nrow * 20 + ks2 * 8 + c + 4];
                mma_f16(sacc[nt], a, bb2);
            }
        }
        #pragma unroll
        for (int nt = 0; nt < 4; nt++) {
            int colb = (ntb + nt) * 8 + 2 * c;
            #pragma unroll
            for (int e = 0; e < 2; e++) {
                int col = colb + e;
                if (col < 49) {
                    if (r0 < 49) ss[r0 * 52 + col] = fmaf(sacc[nt][e],     ATT_SCALE, ss[r0 * 52 + col]);
                    if (r1 < 49) ss[r1 * 52 + col] = fmaf(sacc[nt][2 + e], ATT_SCALE, ss[r1 * 52 + col]);
                }
            }
        }
    }
    __syncthreads();

    for (int n = warp; n < 49; n += 8) {
        float e0 = ss[n * 52 + lane];
        float e1 = (lane + 32 < 49) ? ss[n * 52 + lane + 32] : -1e30f;
        float mx = fmaxf(e0, e1);
        #pragma unroll
        for (int o = 16; o; o >>= 1) mx = fmaxf(mx, __shfl_xor_sync(0xffffffffu, mx, o));
        float x0 = __expf(e0 - mx);
        float x1 = (lane + 32 < 49) ? __expf(e1 - mx) : 0.f;
        float sm = x0 + x1;
        #pragma unroll
        for (int o = 16; o; o >>= 1) sm += __shfl_xor_sync(0xffffffffu, sm, o);
        float inv = 1.0f / sm;
        ss[n * 52 + lane] = x0 * inv;
        if (lane + 32 < 49) ss[n * 52 + lane + 32] = x1 * inv;
    }
    __syncthreads();

    for (int idx = tid; idx < 49 * 32; idx += 256) {
        int r = idx >> 5, wd = idx & 31;
        int c0 = 2 * wd;
        float v0 = (c0 < 49)     ? ss[r * 52 + c0]     : 0.f;
        float v1 = (c0 + 1 < 49) ? ss[r * 52 + c0 + 1] : 0.f;
        ps[r * 36 + wd] = pack_h2(v0, v1);
    }
    __syncthreads();

    {
        const int nt2b = (warp & 1) * 2;
        float oacc[2][4];
        #pragma unroll
        for (int i = 0; i < 2; i++)
            #pragma unroll
            for (int e = 0; e < 4; e++) oacc[i][e] = 0.f;
        #pragma unroll
        for (int ks4 = 0; ks4 < 4; ks4++) {
            uint32_t a[4];
            a[0] = ps[r0 * 36 + ks4 * 8 + c];
            a[1] = ps[r1 * 36 + ks4 * 8 + c];
            a[2] = ps[r0 * 36 + ks4 * 8 + c + 4];
            a[3] = ps[r1 * 36 + ks4 * 8 + c + 4];
            #pragma unroll
            for (int nt = 0; nt < 2; nt++) {
                int ch = (nt2b + nt) * 8 + g;
                uint32_t bb2[2];
                bb2[0] = vt[ch * 36 + ks4 * 8 + c];
                bb2[1] = vt[ch * 36 + ks4 * 8 + c + 4];
                mma_f16(oacc[nt], a, bb2);
            }
        }
        #pragma unroll
        for (int nt = 0; nt < 2; nt++) {
            int chb = (nt2b + nt) * 8 + 2 * c;
            int kch = h * 32 + chb;
            if (r0 < 49)
                g_att_f[afrag_word(gtok[r0], kch, CC)] = pack_h2(oacc[nt][0], oacc[nt][1]);
            if (r1 < 49)
                g_att_f[afrag_word(gtok[r1], kch, CC)] = pack_h2(oacc[nt][2], oacc[nt][3]);
        }
    }
}

// ---------------- depthwise conv + BN (fp16 seq1) -> g_s2_f ----------------
__global__ __launch_bounds__(256) void conv_bn_kernel(
    const float* __restrict__ conv_w,
    const float* __restrict__ bn_g,
    const float* __restrict__ bn_b,
    const float* __restrict__ bn_mean,
    const float* __restrict__ bn_var)
{
    __shared__ uint32_t Sg[32 * 192];
    int blk = blockIdx.x;
    int b   = blk / 98;
    int t0  = (blk % 98) * 32;
    int tid = threadIdx.x;

    #pragma unroll 2
    for (int j = 0; j < 24; j++) {
        int flat = j * 256 + tid;
        int tl = flat / 192, c2 = flat - tl * 192;
        int ch = 2 * c2;
        int hw = t0 + tl;
        int hh = hw / SIDE, ww = hw - hh * SIDE;
        float a0 = 0.f, a1 = 0.f;
        #pragma unroll
        for (int dy = 0; dy < 3; dy++) {
            int y = hh + dy - 1;
            if (y < 0 || y >= SIDE) continue;
            #pragma unroll
            for (int dx = 0; dx < 3; dx++) {
                int xx = ww + dx - 1;
                if (xx < 0 || xx >= SIDE) continue;
                float2 v = unpack_h2(g_seq1h[((size_t)(b * HWD + y * SIDE + xx) * CC + ch) >> 1]);
                a0 = fmaf(v.x, __ldg(&conv_w[ch * 9 + dy * 3 + dx]), a0);
                a1 = fmaf(v.y, __ldg(&conv_w[(ch + 1) * 9 + dy * 3 + dx]), a1);
            }
        }
        float sc0 = __ldg(&bn_g[ch])     * rsqrtf(__ldg(&bn_var[ch])     + LN_EPS);
        float sc1 = __ldg(&bn_g[ch + 1]) * rsqrtf(__ldg(&bn_var[ch + 1]) + LN_EPS);
        float r0 = (a0 - __ldg(&bn_mean[ch]))     * sc0 + __ldg(&bn_b[ch]);
        float r1 = (a1 - __ldg(&bn_mean[ch + 1])) * sc1 + __ldg(&bn_b[ch + 1]);
        Sg[tl * 192 + c2] = pack_h2(r0, r1);
    }
    __syncthreads();

    int m_base = b * HWD + t0;
    int R = m_base >> 7, q0 = (m_base & 127) >> 4;
    int inner = tid & 127;
    int g = inner >> 4, c = (inner >> 2) & 3, chi = (inner >> 1) & 1, hm = inner & 1;
    #pragma unroll 4
    for (int j = 0; j < 24; j++) {
        int combo = j * 2 + (tid >> 7);
        int ko = combo >> 1, qi = combo & 1;
        int tl = qi * 16 + hm * 8 + g;
        int kw = ko * 8 + chi * 4 + c;
        g_s2_f[(((size_t)R * 24 + ko) * 8 + (q0 + qi)) * 128 + inner] = Sg[tl * 192 + kw];
    }
}

// ---------------------------------------------------------------------------
extern "C" void kernel_launch(void* const* d_in, const int* in_sizes, int n_in,
                              void* d_out, int out_size) {
    const float* x          = (const float*)d_in[0];
    const float* ln_g       = (const float*)d_in[1];
    const float* ln_b       = (const float*)d_in[2];
    const float* qkv_w      = (const float*)d_in[3];
    const float* qkv_b      = (const float*)d_in[4];
    const float* proj_w     = (const float*)d_in[5];
    const float* proj_b     = (const float*)d_in[6];
    const float* bias_table = (const float*)d_in[7];
    const float* conv_w     = (const float*)d_in[8];
    const float* bn_g       = (const float*)d_in[9];
    const float* bn_b       = (const float*)d_in[10];
    const float* bn_mean    = (const float*)d_in[11];
    const float* bn_var     = (const float*)d_in[12];
    const float* w1         = (const float*)d_in[13];
    const float* b1         = (const float*)d_in[14];
    const float* w2         = (const float*)d_in[15];
    const float* b2         = (const float*)d_in[16];
    float* out = (float*)d_out;

    const int LN_SMEM = 384 * 33 * 4;
    const int G_SMEM  = 98304;

    cudaFuncSetAttribute(ln_xn_kernel, cudaFuncAttributeMaxDynamicSharedMemorySize, LN_SMEM);
    cudaFuncSetAttribute(hgemm<0>, cudaFuncAttributeMaxDynamicSharedMemorySize, G_SMEM);
    cudaFuncSetAttribute(hgemm<1>, cudaFuncAttributeMaxDynamicSharedMemorySize, G_SMEM);
    cudaFuncSetAttribute(hgemm<2>, cudaFuncAttributeMaxDynamicSharedMemorySize, G_SMEM);
    cudaFuncSetAttribute(hgemm<3>, cudaFuncAttributeMaxDynamicSharedMemorySize, G_SMEM);

    uint32_t* wq; cudaGetSymbolAddress((void**)&wq, g_wq);
    uint32_t* wp; cudaGetSymbolAddress((void**)&wp, g_wp);
    uint32_t* wh1; cudaGetSymbolAddress((void**)&wh1, g_w1);
    uint32_t* wh2; cudaGetSymbolAddress((void**)&wh2, g_w2);

    // launch order: ncu capture (4th launch) lands on hgemm<0>
    pack_a_kernel<<<864 + 288 + 120, 256>>>(qkv_w, wq, proj_w, wp, bias_table);
    ln_xn_kernel<<<TOKENS / 32, 256, LN_SMEM>>>(x, ln_g, ln_b);
    pack_b_kernel<<<1152 + 1152, 256>>>(w1, wh1, w2, wh2);
    hgemm<0><<<dim3(QKVN / 128, TOKENS / 128), 128, G_SMEM>>>(nullptr, wq, qkv_b, nullptr);
    attn_kernel<<<NWIN * NHEADS, 256>>>();
    hgemm<1><<<dim3(CC / 128, TOKENS / 128), 128, G_SMEM>>>(x, wp, proj_b, nullptr);
    conv_bn_kernel<<<TOKENS / 32, 256>>>(conv_w, bn_g, bn_b, bn_mean, bn_var);
    hgemm<2><<<dim3(HIDDEN / 128, TOKENS / 128), 128, G_SMEM>>>(nullptr, wh1, b1, nullptr);
    hgemm<3><<<dim3(CC / 128, TOKENS / 128), 128, G_SMEM>>>(nullptr, wh2, b2, out);
}

// round 17
// speedup vs baseline: 1.0198x; 1.0198x over previous
#include <cuda_runtime.h>
#include <cuda_fp16.h>
#include <math.h>
#include <stdint.h>

#define CC      384
#define SIDE    56
#define HWD     3136
#define TOKENS  100352
#define NHEADS  12
#define NWIN    2048
#define HIDDEN  1536
#define QKVN    1152
#define LN_EPS  1e-5f
#define ATT_SCALE 0.17677669529663687f

// ---------------- scratch ----------------
__device__ uint32_t g_xn_f [(size_t)TOKENS * CC / 2];
__device__ uint32_t g_att_f[(size_t)TOKENS * CC / 2];
__device__ uint32_t g_s2_f [(size_t)TOKENS * CC / 2];
__device__ uint32_t g_hid_f[(size_t)TOKENS * HIDDEN / 2];
__device__ uint32_t g_qkv_w[(size_t)TOKENS * QKVN / 2];   // fp16 row-major
__device__ uint32_t g_seq1h[(size_t)TOKENS * CC / 2];     // fp16 row-major
__device__ uint32_t g_wq[(size_t)QKVN * CC / 2];
__device__ uint32_t g_wp[(size_t)CC * CC / 2];
__device__ uint32_t g_w1[(size_t)HIDDEN * CC / 2];
__device__ uint32_t g_w2[(size_t)CC * HIDDEN / 2];

// A-fragment word address
__device__ __forceinline__ size_t afrag_word(int m, int k, int K) {
    int R = m >> 7, q = (m & 127) >> 4, hm = (m >> 3) & 1, g = m & 7;
    int ko = k >> 4, chi = (k >> 3) & 1, c = (k & 7) >> 1;
    return (((size_t)R * (K / 16) + ko) * 8 + q) * 128 + g * 16 + c * 4 + chi * 2 + hm;
}
// B-fragment word address
__device__ __forceinline__ size_t bfrag_word(int n, int k, int K) {
    int RN = n >> 7, nq = (n & 127) >> 3, g = n & 7;
    int ko = k >> 4, chi = (k >> 3) & 1, c = (k & 7) >> 1;
    return (((size_t)RN * (K / 16) + ko) * 16 + nq) * 64 + g * 8 + c * 2 + chi;
}

__device__ __forceinline__ uint32_t pack_h2(float a, float b) {
    __half2 h = __floats2half2_rn(a, b);
    return *reinterpret_cast<uint32_t*>(&h);
}
__device__ __forceinline__ float2 unpack_h2(uint32_t w) {
    __half2 h = *reinterpret_cast<__half2*>(&w);
    return __half22float2(h);
}

__device__ __forceinline__ void mma_f16(float* d, const uint32_t* a, const uint32_t* b) {
    asm volatile(
        "mma.sync.aligned.m16n8k16.row.col.f32.f16.f16.f32 "
        "{%0,%1,%2,%3},{%4,%5,%6,%7},{%8,%9},{%0,%1,%2,%3};"
        : "+f"(d[0]), "+f"(d[1]), "+f"(d[2]), "+f"(d[3])
        : "r"(a[0]), "r"(a[1]), "r"(a[2]), "r"(a[3]), "r"(b[0]), "r"(b[1]));
}

__device__ __forceinline__ void ldsm_x4(uint32_t addr, uint32_t* r) {
    asm volatile("ldmatrix.sync.aligned.m8n8.x4.shared.b16 {%0,%1,%2,%3}, [%4];"
        : "=r"(r[0]), "=r"(r[1]), "=r"(r[2]), "=r"(r[3]) : "r"(addr));
}

#define CPA16(sa, gp)  asm volatile("cp.async.cg.shared.global [%0], [%1], 16;" :: "r"(sa), "l"(gp))
#define CPA_COMMIT()   asm volatile("cp.async.commit_group;")
#define CPA_WAIT(n)    asm volatile("cp.async.wait_group %0;" :: "n"(n))

// ---------------- weight pack ----------------
__device__ __forceinline__ void pack_one(const float* W, uint32_t* dst, int N, int K, int idx) {
    if (idx >= N * (K / 2)) return;
    int n = idx / (K / 2);
    int k = (idx - n * (K / 2)) * 2;
    dst[bfrag_word(n, k, K)] = pack_h2(W[(size_t)n * K + k], W[(size_t)n * K + k + 1]);
}
__global__ void pack_a_kernel(const float* __restrict__ Wq, uint32_t* dq,
                              const float* __restrict__ Wp, uint32_t* dp) {
    int bid = blockIdx.x;
    if (bid < 864) pack_one(Wq, dq, QKVN, CC, bid * 256 + threadIdx.x);
    else           pack_one(Wp, dp, CC, CC, (bid - 864) * 256 + threadIdx.x);
}
__global__ void pack_b_kernel(const float* __restrict__ W1, uint32_t* d1,
                              const float* __restrict__ W2, uint32_t* d2) {
    int bid = blockIdx.x;
    if (bid < 1152) pack_one(W1, d1, HIDDEN, CC, bid * 256 + threadIdx.x);
    else            pack_one(W2, d2, CC, HIDDEN, (bid - 1152) * 256 + threadIdx.x);
}

// ---------------- LayerNorm -> g_xn_f (A-fragment fp16) --------------------
__global__ __launch_bounds__(256) void ln_xn_kernel(
    const float* __restrict__ x,
    const float* __restrict__ lng,
    const float* __restrict__ lnb)
{
    extern __shared__ float S[];               // [384][33]
    __shared__ float red[2][8][32];
    __shared__ float s_mu[32], s_rs[32];
    int blk = blockIdx.x;
    int b   = blk / 98;
    int t0  = (blk % 98) * 32;
    int tid = threadIdx.x;

    const float* xb = x + (size_t)b * CC * HWD + t0;
    #pragma unroll 4
    for (int it = 0; it < 48; it++) {
        int idx = it * 256 + tid;
        int c = idx >> 5, t = idx & 31;
        S[c * 33 + t] = xb[(size_t)c * HWD + t];
    }
    __syncthreads();

    int t = tid & 31, p = tid >> 5;
    float s = 0.f, ss = 0.f;
    #pragma unroll 8
    for (int j = 0; j < 48; j++) {
        float v = S[(p + 8 * j) * 33 + t];
        s += v; ss += v * v;
    }
    red[0][p][t] = s; red[1][p][t] = ss;
    __syncthreads();
    if (p == 0) {
        float Sm = 0.f, SS = 0.f;
        #pragma unroll
        for (int q = 0; q < 8; q++) { Sm += red[0][q][t]; SS += red[1][q][t]; }
        float mu = Sm * (1.0f / CC);
        float var = SS * (1.0f / CC) - mu * mu;
        s_mu[t] = mu;
        s_rs[t] = rsqrtf(var + LN_EPS);
    }
    __syncthreads();

    int m_base = b * HWD + t0;
    int R = m_base >> 7, q0 = (m_base & 127) >> 4;
    int inner = tid & 127;
    int g = inner >> 4, c = (inner >> 2) & 3, chi = (inner >> 1) & 1, hm = inner & 1;
    #pragma unroll 4
    for (int j = 0; j < 24; j++) {
        int combo = j * 2 + (tid >> 7);
        int ko = combo >> 1, qi = combo & 1;
        int tl = qi * 16 + hm * 8 + g;
        int k  = ko * 16 + chi * 8 + c * 2;
        float mu = s_mu[tl], rs = s_rs[tl];
        float v0 = (S[k * 33 + tl]       - mu) * rs * __ldg(&lng[k])     + __ldg(&lnb[k]);
        float v1 = (S[(k + 1) * 33 + tl] - mu) * rs * __ldg(&lng[k + 1]) + __ldg(&lnb[k + 1]);
        g_xn_f[(((size_t)R * 24 + ko) * 8 + (q0 + qi)) * 128 + inner] = pack_h2(v0, v1);
    }
}

// ---------------- fp16 tensor-core GEMM (128 thr, 2x2 warps of 64x64) ------
template<int MODE>
__global__ __launch_bounds__(128, 2) void hgemm(
    const float* __restrict__ x,
    const uint32_t* __restrict__ Bw,
    const float* __restrict__ bias,
    float* __restrict__ out)
{
    constexpr int K    = (MODE == 3) ? HIDDEN : CC;
    constexpr int KD16 = K / 16;
    constexpr int KT   = K / 64;
    const int m0  = blockIdx.y * 128;
    const int n0  = blockIdx.x * 128;
    const int tid = threadIdx.x;
    const int lane = tid & 31, warp = tid >> 5;
    const int wr = warp >> 1, wc = warp & 1;   // 2x2 warps; warp tile 64x64
    const int g  = lane >> 2, c = lane & 3;

    extern __shared__ uint32_t smu[];
    const uint32_t smem_base = (uint32_t)__cvta_generic_to_shared(smu);
    float* smf = (float*)smu;

    const uint32_t* Asrc = (MODE == 0) ? g_xn_f : (MODE == 1) ? g_att_f
                         : (MODE == 2) ? g_s2_f : g_hid_f;
    const size_t Abase = (size_t)(m0 >> 7) * KD16 * 1024;
    const size_t Bbase = (size_t)(n0 >> 7) * KD16 * 1024;

    float acc[4][8][4];
    #pragma unroll
    for (int i = 0; i < 4; i++)
        #pragma unroll
        for (int j = 0; j < 8; j++)
            #pragma unroll
            for (int e = 0; e < 4; e++) acc[i][j][e] = 0.f;

    auto load_tile = [&](int kt) {
        int st = kt % 3;
        const uint32_t* Ag = Asrc + Abase + (size_t)kt * 4096;
        const uint32_t* Bg = Bw   + Bbase + (size_t)kt * 4096;
        uint32_t As = smem_base + st * 32768;
        #pragma unroll
        for (int i = 0; i < 8; i++) {
            CPA16(As + i * 2048 + tid * 16,         Ag + i * 512 + tid * 4);
            CPA16(As + 16384 + i * 2048 + tid * 16, Bg + i * 512 + tid * 4);
        }
        CPA_COMMIT();
    };

    auto compute = [&](int kt) {
        const uint32_t* S = smu + (kt % 3) * 8192;
        #pragma unroll
        for (int kl = 0; kl < 4; kl++) {
            const uint32_t* A = S + kl * 1024;
            const uint32_t* B = S + 4096 + kl * 1024;
            uint4 af[4];
            uint2 bf[8];
            #pragma unroll
            for (int mi = 0; mi < 4; mi++)
                af[mi] = *(const uint4*)(A + (wr * 4 + mi) * 128 + g * 16 + c * 4);
            #pragma unroll
            for (int ni = 0; ni < 8; ni++)
                bf[ni] = *(const uint2*)(B + (wc * 8 + ni) * 64 + g * 8 + c * 2);
            #pragma unroll
            for (int mi = 0; mi < 4; mi++)
                #pragma unroll
                for (int ni = 0; ni < 8; ni++)
                    mma_f16(acc[mi][ni], &af[mi].x, &bf[ni].x);
        }
    };

    load_tile(0);
    load_tile(1);
    load_tile(2);
    for (int kt = 0; kt < KT; kt++) {
        CPA_WAIT(2);
        __syncthreads();
        compute(kt);
        __syncthreads();
        if (kt + 3 < KT) load_tile(kt + 3); else CPA_COMMIT();
    }
    CPA_WAIT(0);
    __syncthreads();

    // ---- epilogues ----
    if constexpr (MODE == 0) {
        #pragma unroll
        for (int mi = 0; mi < 4; mi++) {
            #pragma unroll
            for (int ni = 0; ni < 8; ni++) {
                int n = n0 + wc * 64 + ni * 8 + 2 * c;
                float b0 = __ldg(&bias[n]), b1 = __ldg(&bias[n + 1]);
                #pragma unroll
                for (int hm = 0; hm < 2; hm++) {
                    int m = m0 + wr * 64 + mi * 16 + hm * 8 + g;
                    g_qkv_w[(size_t)m * (QKVN / 2) + (n >> 1)] =
                        pack_h2(acc[mi][ni][2 * hm] + b0, acc[mi][ni][2 * hm + 1] + b1);
                }
            }
        }
    } else if constexpr (MODE == 2) {
        #pragma unroll
        for (int mi = 0; mi < 4; mi++) {
            int q = wr * 4 + mi;
            #pragma unroll
            for (int np = 0; np < 4; np++) {
                int koW = (n0 >> 4) + wc * 4 + np;
                size_t base = (((size_t)(m0 >> 7) * (HIDDEN / 16) + koW) * 8 + q) * 128;
                float v[2][4];
                #pragma unroll
                for (int chi = 0; chi < 2; chi++) {
                    int ni = np * 2 + chi;
                    int n = n0 + wc * 64 + ni * 8 + 2 * c;
                    float b0 = __ldg(&bias[n]), b1 = __ldg(&bias[n + 1]);
                    #pragma unroll
                    for (int e = 0; e < 4; e++) {
                        float t = acc[mi][ni][e] + ((e & 1) ? b1 : b0);
                        v[chi][e] = 0.5f * t * (1.0f + erff(t * 0.70710678118654752f));
                    }
                }
                uint4 wrd;
                wrd.x = pack_h2(v[0][0], v[0][1]);
                wrd.y = pack_h2(v[0][2], v[0][3]);
                wrd.z = pack_h2(v[1][0], v[1][1]);
                wrd.w = pack_h2(v[1][2], v[1][3]);
                *(uint4*)(g_hid_f + base + g * 16 + c * 4) = wrd;
            }
        }
    } else if constexpr (MODE == 1) {
        float* Xs = smf;
        {
            int m = m0 + tid;
            int bb = m / HWD, hw = m % HWD;
            const float* xb = x + (size_t)bb * CC * HWD + hw;
            #pragma unroll 8
            for (int j = 0; j < 128; j++)
                Xs[tid * 132 + j] = xb[(size_t)(n0 + j) * HWD];
        }
        __syncthreads();
        #pragma unroll
        for (int mi = 0; mi < 4; mi++) {
            #pragma unroll
            for (int ni = 0; ni < 8; ni++) {
                int n  = n0 + wc * 64 + ni * 8 + 2 * c;
                int cn = wc * 64 + ni * 8 + 2 * c;
                float b0 = __ldg(&bias[n]), b1 = __ldg(&bias[n + 1]);
                #pragma unroll
                for (int hm = 0; hm < 2; hm++) {
                    int r = wr * 64 + mi * 16 + hm * 8 + g;
                    int m = m0 + r;
                    float v0 = acc[mi][ni][2 * hm]     + b0 + Xs[r * 132 + cn];
                    float v1 = acc[mi][ni][2 * hm + 1] + b1 + Xs[r * 132 + cn + 1];
                    g_seq1h[((size_t)m * CC + n) >> 1] = pack_h2(v0, v1);
                }
            }
        }
    } else {  // MODE 3
        float* Cs = smf;
        #pragma unroll
        for (int mi = 0; mi < 4; mi++) {
            #pragma unroll
            for (int ni = 0; ni < 8; ni++) {
                int n  = n0 + wc * 64 + ni * 8 + 2 * c;
                int cn = wc * 64 + ni * 8 + 2 * c;
                float b0 = __ldg(&bias[n]), b1 = __ldg(&bias[n + 1]);
                #pragma unroll
                for (int hm = 0; hm < 2; hm++) {
                    int r = wr * 64 + mi * 16 + hm * 8 + g;
                    int m = m0 + r;
                    float2 s2 = unpack_h2(g_s2_f[afrag_word(m, n, CC)]);
                    Cs[r * 132 + cn]     = acc[mi][ni][2 * hm]     + b0 + s2.x;
                    Cs[r * 132 + cn + 1] = acc[mi][ni][2 * hm + 1] + b1 + s2.y;
                }
            }
        }
        __syncthreads();
        int m = m0 + tid;
        int bb = m / HWD, hw = m % HWD;
        float* ob = out + (size_t)bb * CC * HWD + hw;
        #pragma unroll 8
        for (int j = 0; j < 128; j++)
            ob[(size_t)(n0 + j) * HWD] = Cs[tid * 132 + j];
    }
}

// ---------------- windowed attention (tensor-core mma + ldmatrix) ----------
__global__ __launch_bounds__(256) void attn_kernel(const float* __restrict__ bias_table) {
    int wh = blockIdx.x;
    int w  = wh / NHEADS;
    int h  = wh - w * NHEADS;
    int b  = w >> 6;
    int wri = w & 63;
    int nh = wri >> 3, nw = wri & 7;
    int tid = threadIdx.x;
    const int lane = tid & 31, warp = tid >> 5;
    const int g = lane >> 2, c = lane & 3;

    __shared__ uint32_t qs[64 * 20];
    __shared__ uint32_t ks[64 * 20];
    __shared__ uint32_t vt[32 * 36];
    __shared__ uint32_t ps[64 * 36];
    __shared__ float    ss[49 * 52];
    __shared__ float    sbias[169];
    __shared__ int      gtok[49];
    __half* vth = (__half*)vt;

    const uint32_t qs_b = (uint32_t)__cvta_generic_to_shared(qs);
    const uint32_t ks_b = (uint32_t)__cvta_generic_to_shared(ks);
    const uint32_t vt_b = (uint32_t)__cvta_generic_to_shared(vt);
    const uint32_t ps_b = (uint32_t)__cvta_generic_to_shared(ps);

    if (tid < 49) {
        int i = tid / 7, j = tid - i * 7;
        gtok[tid] = b * HWD + (nh * 7 + i) * SIDE + (nw * 7 + j);
    }
    if (tid < 169) sbias[tid] = __ldg(&bias_table[tid * NHEADS + h]);
    __syncthreads();

    for (int idx = tid; idx < 49 * 16; idx += 256) {
        int n = idx >> 4, dp = idx & 15;
        size_t base = (size_t)gtok[n] * (QKVN / 2) + h * 16 + dp;
        qs[n * 20 + dp] = g_qkv_w[base];
        ks[n * 20 + dp] = g_qkv_w[base + 192];
        uint32_t vv = g_qkv_w[base + 384];
        __half2 hv = *reinterpret_cast<__half2*>(&vv);
        vth[(2 * dp) * 72 + n]     = __low2half(hv);
        vth[(2 * dp + 1) * 72 + n] = __high2half(hv);
    }
    for (int t = tid; t < 32 * 15; t += 256) {
        int ch = t / 15, tt = 49 + (t - ch * 15);
        vth[ch * 72 + tt] = __float2half(0.f);
    }
    __syncthreads();

    const int mt = warp >> 1;
    const int ntb = (warp & 1) * 4;
    const int r0 = mt * 16 + g, r1 = r0 + 8;

    // ---- QK^T via mma + ldmatrix ----
    {
        float sacc[4][4];
        #pragma unroll
        for (int i = 0; i < 4; i++)
            #pragma unroll
            for (int e = 0; e < 4; e++) sacc[i][e] = 0.f;
        const int arow = mt * 16 + (lane & 15);
        const int achk = lane >> 4;
        #pragma unroll
        for (int ks2 = 0; ks2 < 2; ks2++) {
            uint32_t a[4];
            ldsm_x4(qs_b + (uint32_t)(arow * 20 + ks2 * 8 + achk * 4) * 4, a);
            uint32_t bfr[4][2];
            #pragma unroll
            for (int ip = 0; ip < 2; ip++) {
                int brow = (ntb + 2 * ip + (lane >> 4)) * 8 + (lane & 7);
                int bchk = (lane >> 3) & 1;
                uint32_t t4[4];
                ldsm_x4(ks_b + (uint32_t)(brow * 20 + ks2 * 8 + bchk * 4) * 4, t4);
                bfr[2 * ip][0] = t4[0]; bfr[2 * ip][1] = t4[1];
                bfr[2 * ip + 1][0] = t4[2]; bfr[2 * ip + 1][1] = t4[3];
            }
            #pragma unroll
            for (int nt = 0; nt < 4; nt++)
                mma_f16(sacc[nt], a, bfr[nt]);
        }
        int i1r0 = r0 / 7, j1r0 = r0 - 7 * i1r0;
        int i1r1 = r1 / 7, j1r1 = r1 - 7 * i1r1;
        #pragma unroll
        for (int nt = 0; nt < 4; nt++) {
            int colb = (ntb + nt) * 8 + 2 * c;
            #pragma unroll
            for (int e = 0; e < 2; e++) {
                int col = colb + e;
                if (col < 49) {
                    int i2 = col / 7, j2 = col - 7 * i2;
                    if (r0 < 49)
                        ss[r0 * 52 + col] = sacc[nt][e] * ATT_SCALE
                            + sbias[(i1r0 - i2 + 6) * 13 + (j1r0 - j2 + 6)];
                    if (r1 < 49)
                        ss[r1 * 52 + col] = sacc[nt][2 + e] * ATT_SCALE
                            + sbias[(i1r1 - i2 + 6) * 13 + (j1r1 - j2 + 6)];
                }
            }
        }
    }
    __syncthreads();

    // ---- softmax ----
    for (int n = warp; n < 49; n += 8) {
        float e0 = ss[n * 52 + lane];
        float e1 = (lane + 32 < 49) ? ss[n * 52 + lane + 32] : -1e30f;
        float mx = fmaxf(e0, e1);
        #pragma unroll
        for (int o = 16; o; o >>= 1) mx = fmaxf(mx, __shfl_xor_sync(0xffffffffu, mx, o));
        float x0 = __expf(e0 - mx);
        float x1 = (lane + 32 < 49) ? __expf(e1 - mx) : 0.f;
        float sm = x0 + x1;
        #pragma unroll
        for (int o = 16; o; o >>= 1) sm += __shfl_xor_sync(0xffffffffu, sm, o);
        float inv = 1.0f / sm;
        ss[n * 52 + lane] = x0 * inv;
        if (lane + 32 < 49) ss[n * 52 + lane + 32] = x1 * inv;
    }
    __syncthreads();

    // ---- pack probs to fp16 (pad cols -> 0) ----
    for (int idx = tid; idx < 49 * 32; idx += 256) {
        int r = idx >> 5, wd = idx & 31;
        int c0 = 2 * wd;
        float v0 = (c0 < 49)     ? ss[r * 52 + c0]     : 0.f;
        float v1 = (c0 + 1 < 49) ? ss[r * 52 + c0 + 1] : 0.f;
        ps[r * 36 + wd] = pack_h2(v0, v1);
    }
    __syncthreads();

    // ---- AV via mma + ldmatrix ----
    {
        const int nt2b = (warp & 1) * 2;
        float oacc[2][4];
        #pragma unroll
        for (int i = 0; i < 2; i++)
            #pragma unroll
            for (int e = 0; e < 4; e++) oacc[i][e] = 0.f;
        const int arow = mt * 16 + (lane & 15);
        const int achk = lane >> 4;
        const int brow = (nt2b + (lane >> 4)) * 8 + (lane & 7);
        const int bchk = (lane >> 3) & 1;
        #pragma unroll
        for (int ks4 = 0; ks4 < 4; ks4++) {
            uint32_t a[4];
            ldsm_x4(ps_b + (uint32_t)(arow * 36 + ks4 * 8 + achk * 4) * 4, a);
            uint32_t t4[4];
            ldsm_x4(vt_b + (uint32_t)(brow * 36 + ks4 * 8 + bchk * 4) * 4, t4);
            mma_f16(oacc[0], a, t4);
            mma_f16(oacc[1], a, t4 + 2);
        }
        #pragma unroll
        for (int nt = 0; nt < 2; nt++) {
            int chb = (nt2b + nt) * 8 + 2 * c;
            int kch = h * 32 + chb;
            if (r0 < 49)
                g_att_f[afrag_word(gtok[r0], kch, CC)] = pack_h2(oacc[nt][0], oacc[nt][1]);
            if (r1 < 49)
                g_att_f[afrag_word(gtok[r1], kch, CC)] = pack_h2(oacc[nt][2], oacc[nt][3]);
        }
    }
}

// ---------------- depthwise conv + BN (fp16 seq1) -> g_s2_f ----------------
__global__ __launch_bounds__(256) void conv_bn_kernel(
    const float* __restrict__ conv_w,
    const float* __restrict__ bn_g,
    const float* __restrict__ bn_b,
    const float* __restrict__ bn_mean,
    const float* __restrict__ bn_var)
{
    __shared__ uint32_t Sg[32 * 192];
    int blk = blockIdx.x;
    int b   = blk / 98;
    int t0  = (blk % 98) * 32;
    int tid = threadIdx.x;

    #pragma unroll 2
    for (int j = 0; j < 24; j++) {
        int flat = j * 256 + tid;
        int tl = flat / 192, c2 = flat - tl * 192;
        int ch = 2 * c2;
        int hw = t0 + tl;
        int hh = hw / SIDE, ww = hw - hh * SIDE;
        float a0 = 0.f, a1 = 0.f;
        #pragma unroll
        for (int dy = 0; dy < 3; dy++) {
            int y = hh + dy - 1;
            if (y < 0 || y >= SIDE) continue;
            #pragma unroll
            for (int dx = 0; dx < 3; dx++) {
                int xx = ww + dx - 1;
                if (xx < 0 || xx >= SIDE) continue;
                float2 v = unpack_h2(g_seq1h[((size_t)(b * HWD + y * SIDE + xx) * CC + ch) >> 1]);
                a0 = fmaf(v.x, __ldg(&conv_w[ch * 9 + dy * 3 + dx]), a0);
                a1 = fmaf(v.y, __ldg(&conv_w[(ch + 1) * 9 + dy * 3 + dx]), a1);
            }
        }
        float sc0 = __ldg(&bn_g[ch])     * rsqrtf(__ldg(&bn_var[ch])     + LN_EPS);
        float sc1 = __ldg(&bn_g[ch + 1]) * rsqrtf(__ldg(&bn_var[ch + 1]) + LN_EPS);
        float r0 = (a0 - __ldg(&bn_mean[ch]))     * sc0 + __ldg(&bn_b[ch]);
        float r1 = (a1 - __ldg(&bn_mean[ch + 1])) * sc1 + __ldg(&bn_b[ch + 1]);
        Sg[tl * 192 + c2] = pack_h2(r0, r1);
    }
    __syncthreads();

    int m_base = b * HWD + t0;
    int R = m_base >> 7, q0 = (m_base & 127) >> 4;
    int inner = tid & 127;
    int g = inner >> 4, c = (inner >> 2) & 3, chi = (inner >> 1) & 1, hm = inner & 1;
    #pragma unroll 4
    for (int j = 0; j < 24; j++) {
        int combo = j * 2 + (tid >> 7);
        int ko = combo >> 1, qi = combo & 1;
        int tl = qi * 16 + hm * 8 + g;
        int kw = ko * 8 + chi * 4 + c;
        g_s2_f[(((size_t)R * 24 + ko) * 8 + (q0 + qi)) * 128 + inner] = Sg[tl * 192 + kw];
    }
}

// ---------------------------------------------------------------------------
extern "C" void kernel_launch(void* const* d_in, const int* in_sizes, int n_in,
                              void* d_out, int out_size) {
    const float* x          = (const float*)d_in[0];
    const float* ln_g       = (const float*)d_in[1];
    const float* ln_b       = (const float*)d_in[2];
    const float* qkv_w      = (const float*)d_in[3];
    const float* qkv_b      = (const float*)d_in[4];
    const float* proj_w     = (const float*)d_in[5];
    const float* proj_b     = (const float*)d_in[6];
    const float* bias_table = (const float*)d_in[7];
    const float* conv_w     = (const float*)d_in[8];
    const float* bn_g       = (const float*)d_in[9];
    const float* bn_b       = (const float*)d_in[10];
    const float* bn_mean    = (const float*)d_in[11];
    const float* bn_var     = (const float*)d_in[12];
    const float* w1         = (const float*)d_in[13];
    const float* b1         = (const float*)d_in[14];
    const float* w2         = (const float*)d_in[15];
    const float* b2         = (const float*)d_in[16];
    float* out = (float*)d_out;

    const int LN_SMEM = 384 * 33 * 4;
    const int G_SMEM  = 98304;

    cudaFuncSetAttribute(ln_xn_kernel, cudaFuncAttributeMaxDynamicSharedMemorySize, LN_SMEM);
    cudaFuncSetAttribute(hgemm<0>, cudaFuncAttributeMaxDynamicSharedMemorySize, G_SMEM);
    cudaFuncSetAttribute(hgemm<1>, cudaFuncAttributeMaxDynamicSharedMemorySize, G_SMEM);
    cudaFuncSetAttribute(hgemm<2>, cudaFuncAttributeMaxDynamicSharedMemorySize, G_SMEM);
    cudaFuncSetAttribute(hgemm<3>, cudaFuncAttributeMaxDynamicSharedMemorySize, G_SMEM);

    uint32_t* wq; cudaGetSymbolAddress((void**)&wq, g_wq);
    uint32_t* wp; cudaGetSymbolAddress((void**)&wp, g_wp);
    uint32_t* wh1; cudaGetSymbolAddress((void**)&wh1, g_w1);
    uint32_t* wh2; cudaGetSymbolAddress((void**)&wh2, g_w2);

    // launch order: ncu capture (4th launch) lands on hgemm<0>
    pack_a_kernel<<<864 + 288, 256>>>(qkv_w, wq, proj_w, wp);
    ln_xn_kernel<<<TOKENS / 32, 256, LN_SMEM>>>(x, ln_g, ln_b);
    pack_b_kernel<<<1152 + 1152, 256>>>(w1, wh1, w2, wh2);
    hgemm<0><<<dim3(QKVN / 128, TOKENS / 128), 128, G_SMEM>>>(nullptr, wq, qkv_b, nullptr);
    attn_kernel<<<NWIN * NHEADS, 256>>>(bias_table);
    hgemm<1><<<dim3(CC / 128, TOKENS / 128), 128, G_SMEM>>>(x, wp, proj_b, nullptr);
    conv_bn_kernel<<<TOKENS / 32, 256>>>(conv_w, bn_g, bn_b, bn_mean, bn_var);
    hgemm<2><<<dim3(HIDDEN / 128, TOKENS / 128), 128, G_SMEM>>>(nullptr, wh1, b1, nullptr);
    hgemm<3><<<dim3(CC / 128, TOKENS / 128), 128, G_SMEM>>>(nullptr, wh2, b2, out);
}